// round 11
// baseline (speedup 1.0000x reference)
#include <cuda_runtime.h>
#include <cuda.h>
#include <cstdint>
#include <cstring>
#include <dlfcn.h>

// Problem constants (match reference_code)
#define USER_NUM  1000000
#define ITEM_NUM  100000
#define EMBED_DIM 64
#define BATCH     16384

#define THREADS    256
#define E_PER_CTA  64            // elems 0-31: LDG path, 32-63: TMA gather4 path
#define LDG_ELEMS  32
#define TMA_ELEMS  32
#define TMA_ROWS   (TMA_ELEMS * 2)     // 64 rows x 256B = 16KB
#define G4_OPS     (TMA_ROWS / 4)      // 16 gather4 ops per CTA
#define TMA_BYTES  (TMA_ROWS * 256)

// FM scoring: out[e] = w[u] + w[i] + b + dot(V[u], V[i]).  INPUT is int32.
//
// R2-R9: every LSU-path shape saturates at ~1.36TB/s on this random-128B
// gather. TMA gather4 (4 arbitrary rows = 1KB per op) runs on the TMA
// engine with independent transaction tracking. sm_103 requires the
// .shared::cta destination form (R10's .shared::cluster was rejected).
// Split the work across both engines; if caps add -> ~2x.

__device__ __forceinline__ uint32_t smem_u32(const void* p) {
    return (uint32_t)__cvta_generic_to_shared(p);
}

__global__ void __launch_bounds__(THREADS) fm_g4_kernel(
    const __grid_constant__ CUtensorMap tmap,   // V as 2D [rows, 64] f32
    const int*   __restrict__ inp,
    const float* __restrict__ w,
    const float* __restrict__ bptr,
    const float* __restrict__ V,
    float*       __restrict__ out)
{
    __shared__ __align__(1024) float rows[TMA_ROWS][EMBED_DIM];  // 16KB
    __shared__ int      sidx[TMA_ELEMS * 2];
    __shared__ __align__(8) uint64_t mbar;

    const int tid  = threadIdx.x;
    const int e0   = blockIdx.x * E_PER_CTA;
    const int grp  = tid >> 4;       // 0..15
    const int lane = tid & 15;

    // ---- LDG half (elems e0..e0+31): gathers issued immediately ----
    const int4 idx = __ldg(reinterpret_cast<const int4*>(inp) + (e0 >> 1) + grp);
    const long long u0 = (long long)idx.x;
    const long long i0 = (long long)idx.y + USER_NUM;
    const long long u1 = (long long)idx.z;
    const long long i1 = (long long)idx.w + USER_NUM;

    const float4 a0 = __ldg(reinterpret_cast<const float4*>(V + u0 * EMBED_DIM) + lane);
    const float4 c0 = __ldg(reinterpret_cast<const float4*>(V + i0 * EMBED_DIM) + lane);
    const float4 a1 = __ldg(reinterpret_cast<const float4*>(V + u1 * EMBED_DIM) + lane);
    const float4 c1 = __ldg(reinterpret_cast<const float4*>(V + i1 * EMBED_DIM) + lane);

    // ---- Stage TMA-half indices + init mbarrier ----
    if (tid < TMA_ELEMS * 2)
        sidx[tid] = __ldg(&inp[(e0 + LDG_ELEMS) * 2 + tid]);
    if (tid == 0) {
        asm volatile("mbarrier.init.shared.b64 [%0], 1;"
                     :: "r"(smem_u32(&mbar)) : "memory");
    }
    __syncthreads();

    // ---- TMA gather4 half: 16 ops, each fetches 4 arbitrary V rows ----
    if (tid == 0) {
        asm volatile("mbarrier.arrive.expect_tx.shared.b64 _, [%0], %1;"
                     :: "r"(smem_u32(&mbar)), "r"((uint32_t)TMA_BYTES) : "memory");
    }
    if (tid < G4_OPS) {
        // op t covers elems 2t, 2t+1 of the TMA half:
        // rows[4t]=Vu(2t) rows[4t+1]=Vi(2t) rows[4t+2]=Vu(2t+1) rows[4t+3]=Vi(2t+1)
        const int r0 = sidx[4 * tid];
        const int r1 = sidx[4 * tid + 1] + USER_NUM;
        const int r2 = sidx[4 * tid + 2];
        const int r3 = sidx[4 * tid + 3] + USER_NUM;
        const uint32_t dst = smem_u32(&rows[4 * tid][0]);
        asm volatile(
            "cp.async.bulk.tensor.2d.tile::gather4.shared::cta.global."
            "mbarrier::complete_tx::bytes [%0], [%1, {%2, %3, %4, %5, %6}], [%7];"
            :: "r"(dst), "l"(&tmap),
               "r"(0), "r"(r0), "r"(r1), "r"(r2), "r"(r3),
               "r"(smem_u32(&mbar))
            : "memory");
    }

    // ---- w sums for all 4 outputs this group owns (overlapped) ----
    float ws0 = 0.f, ws1 = 0.f, ws2 = 0.f, ws3 = 0.f;
    if (lane == 0) {
        const float bb = __ldg(&bptr[0]);
        ws0 = __ldg(&w[u0]) + __ldg(&w[i0]) + bb;
        ws1 = __ldg(&w[u1]) + __ldg(&w[i1]) + bb;
        const unsigned u2 = (unsigned)sidx[4 * grp];
        const unsigned i2 = (unsigned)sidx[4 * grp + 1] + USER_NUM;
        const unsigned u3 = (unsigned)sidx[4 * grp + 2];
        const unsigned i3 = (unsigned)sidx[4 * grp + 3] + USER_NUM;
        ws2 = __ldg(&w[u2]) + __ldg(&w[i2]) + bb;
        ws3 = __ldg(&w[u3]) + __ldg(&w[i3]) + bb;
    }

    // ---- LDG-half dots (loads have been in flight the whole time) ----
    float d0 = a0.x * c0.x + a0.y * c0.y + a0.z * c0.z + a0.w * c0.w;
    float d1 = a1.x * c1.x + a1.y * c1.y + a1.z * c1.z + a1.w * c1.w;
    #pragma unroll
    for (int off = 8; off > 0; off >>= 1) {
        d0 += __shfl_xor_sync(0xffffffffu, d0, off);
        d1 += __shfl_xor_sync(0xffffffffu, d1, off);
    }
    if (lane == 0)
        *reinterpret_cast<float2*>(out + e0 + 2 * grp) = make_float2(ws0 + d0, ws1 + d1);

    // ---- Wait for gather4 data, then TMA-half dots from SMEM ----
    {
        const uint32_t mb = smem_u32(&mbar);
        asm volatile(
            "{\n\t.reg .pred P;\n\t"
            "W_%=:\n\t"
            "mbarrier.try_wait.parity.shared.b64 P, [%0], 0;\n\t"
            "@P bra D_%=;\n\t"
            "bra W_%=;\n\t"
            "D_%=:\n\t}"
            :: "r"(mb) : "memory");
    }

    const float4 a2 = *reinterpret_cast<const float4*>(&rows[4 * grp][lane * 4]);
    const float4 c2 = *reinterpret_cast<const float4*>(&rows[4 * grp + 1][lane * 4]);
    const float4 a3 = *reinterpret_cast<const float4*>(&rows[4 * grp + 2][lane * 4]);
    const float4 c3 = *reinterpret_cast<const float4*>(&rows[4 * grp + 3][lane * 4]);

    float d2 = a2.x * c2.x + a2.y * c2.y + a2.z * c2.z + a2.w * c2.w;
    float d3 = a3.x * c3.x + a3.y * c3.y + a3.z * c3.z + a3.w * c3.w;
    #pragma unroll
    for (int off = 8; off > 0; off >>= 1) {
        d2 += __shfl_xor_sync(0xffffffffu, d2, off);
        d3 += __shfl_xor_sync(0xffffffffu, d3, off);
    }
    if (lane == 0)
        *reinterpret_cast<float2*>(out + e0 + LDG_ELEMS + 2 * grp) =
            make_float2(ws2 + d2, ws3 + d3);
}

// ---- Fallback: proven pure-LDG kernel (R2, 6.6us) ----
__global__ void __launch_bounds__(256) fm_ldg_kernel(
    const int* __restrict__ inp, const float* __restrict__ w,
    const float* __restrict__ bptr, const float* __restrict__ V,
    float* __restrict__ out)
{
    const int gid  = blockIdx.x * blockDim.x + threadIdx.x;
    const int elem = gid >> 4;
    const int lane = gid & 15;
    if (elem >= BATCH) return;
    const int2 idx = __ldg(reinterpret_cast<const int2*>(inp) + elem);
    const long long u = (long long)idx.x;
    const long long i = (long long)idx.y + USER_NUM;
    const float4 a = __ldg(reinterpret_cast<const float4*>(V + u * EMBED_DIM) + lane);
    const float4 c = __ldg(reinterpret_cast<const float4*>(V + i * EMBED_DIM) + lane);
    float wsum = 0.f;
    if (lane == 0) wsum = __ldg(&w[u]) + __ldg(&w[i]) + __ldg(&bptr[0]);
    float dot = a.x * c.x + a.y * c.y + a.z * c.z + a.w * c.w;
    #pragma unroll
    for (int off = 8; off > 0; off >>= 1)
        dot += __shfl_xor_sync(0xffffffffu, dot, off);
    if (lane == 0) out[elem] = wsum + dot;
}

typedef CUresult (*PFN_tmapEncode)(
    CUtensorMap*, CUtensorMapDataType, cuuint32_t, void*,
    const cuuint64_t*, const cuuint64_t*, const cuuint32_t*, const cuuint32_t*,
    CUtensorMapInterleave, CUtensorMapSwizzle, CUtensorMapL2promotion,
    CUtensorMapFloatOOBfill);

extern "C" void kernel_launch(void* const* d_in, const int* in_sizes, int n_in,
                              void* d_out, int out_size)
{
    const int*   inp = (const int*)d_in[0];
    const float* w   = (const float*)d_in[1];
    const float* b   = (const float*)d_in[2];
    const float* V   = (const float*)d_in[3];
    float*       out = (float*)d_out;

    // Build V tensormap on host (runs at capture time; no device alloc).
    bool ok = false;
    CUtensorMap tmap;
    void* h = dlopen("libcuda.so.1", RTLD_LAZY | RTLD_NOLOAD);
    if (!h) h = dlopen("libcuda.so.1", RTLD_LAZY);
    if (!h) h = dlopen("libcuda.so", RTLD_LAZY);
    PFN_tmapEncode enc = h ? (PFN_tmapEncode)dlsym(h, "cuTensorMapEncodeTiled")
                           : nullptr;
    if (enc) {
        cuuint64_t dims[2]    = {EMBED_DIM, USER_NUM + ITEM_NUM};
        cuuint64_t strides[1] = {EMBED_DIM * sizeof(float)};
        cuuint32_t box[2]     = {EMBED_DIM, 1};
        cuuint32_t estr[2]    = {1, 1};
        ok = enc(&tmap, CU_TENSOR_MAP_DATA_TYPE_FLOAT32, 2, (void*)V,
                 dims, strides, box, estr,
                 CU_TENSOR_MAP_INTERLEAVE_NONE, CU_TENSOR_MAP_SWIZZLE_NONE,
                 CU_TENSOR_MAP_L2_PROMOTION_L2_128B,
                 CU_TENSOR_MAP_FLOAT_OOB_FILL_NONE) == CUDA_SUCCESS;
    }

    if (ok) {
        fm_g4_kernel<<<BATCH / E_PER_CTA, THREADS>>>(tmap, inp, w, b, V, out);
    } else {
        fm_ldg_kernel<<<(BATCH * 16 + 255) / 256, 256>>>(inp, w, b, V, out);
    }
}

// round 12
// speedup vs baseline: 1.0048x; 1.0048x over previous
#include <cuda_runtime.h>
#include <cstdint>

// Problem constants (match reference_code)
#define USER_NUM  1000000
#define EMBED_DIM 64
#define BATCH     16384

// FM scoring: out[e] = w[u] + w[i] + b + dot(V[u], V[i])
//   (0.5*sum((Vu+Vi)^2 - Vu^2 - Vi^2) == sum(Vu*Vi))
// INPUT is int32 on the wire (JAX x64-off downgrades int64->int32).
//
// R2-R11 establish this kernel sits on the chip's random-128B-line service
// wall (~1.37 TB/s), invariant across LDG/cp.async/TMA-bulk/gather4, any
// occupancy, MLP, width, or cache hint. 8.7MB irreducible traffic / 1.37TB/s
// = ~6.2us floor. This is the best-measured shape (16 lanes/elem) with the
// w/b loads hoisted off the critical tail and 32-bit addressing.
__global__ void __launch_bounds__(256) fm_score_kernel(
    const int*   __restrict__ inp,   // [BATCH, 2] int32
    const float* __restrict__ w,     // [USER_NUM + ITEM_NUM]
    const float* __restrict__ bptr,  // [1]
    const float* __restrict__ V,     // [USER_NUM + ITEM_NUM, 64]
    float*       __restrict__ out)   // [BATCH]
{
    const int gid  = blockIdx.x * blockDim.x + threadIdx.x;
    const int elem = gid >> 4;       // 16 lanes per element (grid is exact)
    const int lane = gid & 15;

    // Both indices in one 64-bit broadcast load.
    const int2 idx = __ldg(reinterpret_cast<const int2*>(inp) + elem);
    const unsigned u = (unsigned)idx.x;                 // < 100000
    const unsigned i = (unsigned)idx.y + USER_NUM;      // < 1100000

    // 32-bit element offsets (max 1.1M*64 = 70.4M < 2^31).
    const float* up = V + u * (unsigned)EMBED_DIM;
    const float* ip = V + i * (unsigned)EMBED_DIM;

    // Two 128-bit gathers back-to-back (rows are 256B-aligned).
    const float4 a = __ldg(reinterpret_cast<const float4*>(up) + lane);
    const float4 c = __ldg(reinterpret_cast<const float4*>(ip) + lane);

    // Linear terms issued early, overlapped with the gathers (broadcast
    // loads across the group; only lane 0's value is consumed).
    float wsum = 0.0f;
    if (lane == 0)
        wsum = __ldg(&w[u]) + __ldg(&w[i]) + __ldg(&bptr[0]);

    float dot = a.x * c.x + a.y * c.y + a.z * c.z + a.w * c.w;

    // Reduce across the 16-lane group (contiguous within the warp).
    #pragma unroll
    for (int off = 8; off > 0; off >>= 1)
        dot += __shfl_xor_sync(0xffffffffu, dot, off);

    if (lane == 0)
        out[elem] = wsum + dot;
}

extern "C" void kernel_launch(void* const* d_in, const int* in_sizes, int n_in,
                              void* d_out, int out_size)
{
    const int*   inp = (const int*)d_in[0];    // INPUT int32 [BATCH,2]
    const float* w   = (const float*)d_in[1];  // w
    const float* b   = (const float*)d_in[2];  // b
    const float* V   = (const float*)d_in[3];  // V
    float*       out = (float*)d_out;          // [BATCH,1] float32

    const int threads = 256;
    const int blocks  = (BATCH * 16) / threads;   // 1024, exact
    fm_score_kernel<<<blocks, threads>>>(inp, w, b, V, out);
}